// round 6
// baseline (speedup 1.0000x reference)
#include <cuda_runtime.h>
#include <stdint.h>

// 12-bit ripple-borrow subtractor on binary (0/1) float spikes.
// Boolean-exact collapse: diffs = bits of ((a-b) & 0xFFF) MSB-first,
// borrow = (a < b). Output: [B*12] diffs row-major, then [B] borrow.
//
// R5: persistent grid-stride version of R4 (which hit the ~6.56 TB/s
// mixed-stream ceiling). Grid = 148 SMs x 4 CTAs, fully resident; each CTA
// streams tiles back-to-back -> no wave-quantization tail, no CTA churn.
// Per-instruction address pattern identical to R4/R1 (the measured-best).

#define TPB 256
#define ROWS_PER_THREAD 2
#define TILE_ROWS (TPB * ROWS_PER_THREAD)
#define NUM_BLOCKS (148 * 4)

__device__ __forceinline__ uint32_t pack12(const uint4& w0, const uint4& w1, const uint4& w2) {
    // index 0 = MSB (bit 11) ... index 11 = LSB (bit 0); inputs are 0.0f/1.0f
    uint32_t v = 0;
    v |= (w0.x ? 1u : 0u) << 11;
    v |= (w0.y ? 1u : 0u) << 10;
    v |= (w0.z ? 1u : 0u) << 9;
    v |= (w0.w ? 1u : 0u) << 8;
    v |= (w1.x ? 1u : 0u) << 7;
    v |= (w1.y ? 1u : 0u) << 6;
    v |= (w1.z ? 1u : 0u) << 5;
    v |= (w1.w ? 1u : 0u) << 4;
    v |= (w2.x ? 1u : 0u) << 3;
    v |= (w2.y ? 1u : 0u) << 2;
    v |= (w2.z ? 1u : 0u) << 1;
    v |= (w2.w ? 1u : 0u);
    return v;
}

__device__ __forceinline__ uint32_t bitf(uint32_t d, int bit) {
    return ((d >> bit) & 1u) * 0x3F800000u;  // 1.0f bits or 0
}

__global__ void __launch_bounds__(TPB) sub12_kernel(
    const uint4* __restrict__ A4,
    const uint4* __restrict__ B4,
    uint4* __restrict__ D4,
    float* __restrict__ Borrow,
    int batch)
{
    const int tid = threadIdx.x;
    const int strideRows = gridDim.x * TILE_ROWS;

    for (int tileBase = blockIdx.x * TILE_ROWS; tileBase < batch; tileBase += strideRows) {
        uint4 a[ROWS_PER_THREAD][3], b[ROWS_PER_THREAD][3];
        int rows[ROWS_PER_THREAD];
        bool valid[ROWS_PER_THREAD];

        // Front-batched loads: all 12 LDG.128 issued before any compute.
#pragma unroll
        for (int r = 0; r < ROWS_PER_THREAD; r++) {
            const int i = tileBase + r * TPB + tid;  // block-strided: best warp pattern
            rows[r] = i;
            valid[r] = (i < batch);
            if (valid[r]) {
                const size_t base = (size_t)i * 3;
                a[r][0] = __ldcs(&A4[base + 0]);
                a[r][1] = __ldcs(&A4[base + 1]);
                a[r][2] = __ldcs(&A4[base + 2]);
                b[r][0] = __ldcs(&B4[base + 0]);
                b[r][1] = __ldcs(&B4[base + 1]);
                b[r][2] = __ldcs(&B4[base + 2]);
            }
        }

#pragma unroll
        for (int r = 0; r < ROWS_PER_THREAD; r++) {
            if (!valid[r]) continue;
            const int i = rows[r];

            const uint32_t ia = pack12(a[r][0], a[r][1], a[r][2]);
            const uint32_t ib = pack12(b[r][0], b[r][1], b[r][2]);
            const uint32_t d  = (ia - ib) & 0xFFFu;

            uint4 o0, o1, o2;
            o0.x = bitf(d, 11); o0.y = bitf(d, 10); o0.z = bitf(d, 9); o0.w = bitf(d, 8);
            o1.x = bitf(d, 7);  o1.y = bitf(d, 6);  o1.z = bitf(d, 5); o1.w = bitf(d, 4);
            o2.x = bitf(d, 3);  o2.y = bitf(d, 2);  o2.z = bitf(d, 1); o2.w = bitf(d, 0);

            const size_t base = (size_t)i * 3;
            __stcs(&D4[base + 0], o0);
            __stcs(&D4[base + 1], o1);
            __stcs(&D4[base + 2], o2);
            __stcs(&Borrow[i], __uint_as_float((ia < ib) ? 0x3F800000u : 0u));
        }
    }
}

extern "C" void kernel_launch(void* const* d_in, const int* in_sizes, int n_in,
                              void* d_out, int out_size)
{
    const uint4* A4 = (const uint4*)d_in[0];
    const uint4* B4 = (const uint4*)d_in[1];
    const int batch = in_sizes[0] / 12;

    float* out = (float*)d_out;
    uint4* D4 = (uint4*)out;
    float* Borrow = out + (size_t)batch * 12;

    // Cap grid at the work size (tiny batches), else fully-resident persistent grid.
    int blocks = NUM_BLOCKS;
    const int tiles = (batch + TILE_ROWS - 1) / TILE_ROWS;
    if (tiles < blocks) blocks = tiles;

    sub12_kernel<<<blocks, TPB>>>(A4, B4, D4, Borrow, batch);
}